// round 12
// baseline (speedup 1.0000x reference)
#include <cuda_runtime.h>
#include <cstdint>

#define T_LEN 2048
#define F_DIM 32
#define B_TOT 512
#define BT    (B_TOT * T_LEN)          // 1,048,576 rows

typedef unsigned long long U;          // packed f32x2 carrier

// ---------------- scratch (__device__ globals) ------------------------------
__device__ float g_gx[(size_t)BT * 4 * F_DIM];   // [row][gate][f]  536MB (bias in)
__device__ float g_yx[(size_t)BT * 2 * F_DIM];   // [row][half][f]  268MB (b_lin in half0)

// ---------------- packed fp32x2 helpers ------------------------------------
__device__ __forceinline__ U ffma2(U a, U b, U c) {
    U d; asm("fma.rn.f32x2 %0, %1, %2, %3;" : "=l"(d) : "l"(a), "l"(b), "l"(c));
    return d;
}
__device__ __forceinline__ U add2(U a, U b) {
    U d; asm("add.rn.f32x2 %0, %1, %2;" : "=l"(d) : "l"(a), "l"(b));
    return d;
}
__device__ __forceinline__ U pack2(float lo, float hi) {
    U d; asm("mov.b64 %0, {%1, %2};" : "=l"(d) : "f"(lo), "f"(hi));
    return d;
}
__device__ __forceinline__ float2 unpk(U d) {
    float2 r; asm("mov.b64 {%0, %1}, %2;" : "=f"(r.x), "=f"(r.y) : "l"(d));
    return r;
}
__device__ __forceinline__ float sum4(U a, U b) {
    float2 s = unpk(add2(a, b));
    return s.x + s.y;
}

// ---------------- activations (proven: rel_err 7.9e-7 end-to-end) -----------
__device__ __forceinline__ float tanh_f(float x) {
    float y; asm("tanh.approx.f32 %0, %1;" : "=f"(y) : "f"(x));
    return y;
}
__device__ __forceinline__ float sig_f(float x) {
    return fmaf(tanh_f(0.5f * x), 0.5f, 0.5f);
}
__device__ __forceinline__ float tanh_acc(float x) {   // final output only
    x = fminf(15.0f, fmaxf(-15.0f, x));
    float e = __expf(-2.0f * x);
    return __fdividef(1.0f - e, 1.0f + e);
}

// ============================================================================
// K1: gx[row][g][f] = bias_g + W_ih[g*32+f]·x[row]        (g = 2r, 2r+1)
//     yx[row][r][f] = sum_{j in [16r,16r+16)} W_lin[f][2j+1]·x_j (+b_lin if r=0)
//   CTA = 128 thr = 2 pairs of role-warps; 16-row smem tiles double-buffered.
//   grid 512 @ 4 CTAs/SM = one clean wave on 128 SMs.
// ============================================================================
__global__ void __launch_bounds__(128, 4)
k1_xpre(const float* __restrict__ x,
        const float* __restrict__ W_ih,
        const float* __restrict__ b_ih,
        const float* __restrict__ b_hh,
        const float* __restrict__ W_lin,
        const float* __restrict__ b_lin)
{
    __shared__ __align__(16) float xs[2][16][F_DIM];   // 4KB
    const int tid = threadIdx.x;
    const int w = tid >> 5, f = tid & 31;
    const int pairId = w >> 1, r = w & 1;
    const int g0 = 2 * r;
    const U ZERO = pack2(0.0f, 0.0f);

    U wa[16], wb[16], wo[8];
    {
        const U* pa = (const U*)(W_ih + (size_t)(g0 * 32 + f) * 32);
        const U* pb = (const U*)(W_ih + (size_t)((g0 + 1) * 32 + f) * 32);
#pragma unroll
        for (int k = 0; k < 16; k++) { wa[k] = pa[k]; wb[k] = pb[k]; }
        const float* pl = W_lin + (size_t)f * 64;
#pragma unroll
        for (int k = 0; k < 4; k++) {
            wo[2 * k]     = pack2(pl[32 * r + 8 * k + 1], pl[32 * r + 8 * k + 3]);
            wo[2 * k + 1] = pack2(pl[32 * r + 8 * k + 5], pl[32 * r + 8 * k + 7]);
        }
    }
    const float biasA = b_ih[g0 * 32 + f] + b_hh[g0 * 32 + f];
    const float biasB = b_ih[(g0 + 1) * 32 + f] + b_hh[(g0 + 1) * 32 + f];
    const float biasY = r ? 0.0f : b_lin[f];

    const int base = blockIdx.x * (BT / 512);          // 2048 rows per CTA
    const int nTiles = (BT / 512) / 16;                // 128 tiles
    const int srid = tid >> 3, sseg = tid & 7;

    {   // stage tile 0
        *(ulonglong2*)&xs[0][srid][sseg * 4] =
            *(const ulonglong2*)(x + ((size_t)(base + srid) * 32 + sseg * 4));
    }
    __syncthreads();

    for (int tile = 0; tile < nTiles; tile++) {
        const int cur = tile & 1;
        ulonglong2 nxt;
        const bool have = (tile + 1 < nTiles);
        if (have)
            nxt = *(const ulonglong2*)(x +
                  ((size_t)(base + (tile + 1) * 16 + srid) * 32 + sseg * 4));

        const int row0 = base + tile * 16 + pairId * 8;
#pragma unroll
        for (int rr = 0; rr < 8; rr++) {
            const ulonglong2* xz = (const ulonglong2*)&xs[cur][pairId * 8 + rr][0];
            U a0 = pack2(biasA, 0.f), a1 = ZERO;
            U c0 = pack2(biasB, 0.f), c1 = ZERO;
            U y0 = pack2(biasY, 0.f), y1 = ZERO;
#pragma unroll
            for (int i = 0; i < 8; i++) {
                ulonglong2 v = xz[i];
                a0 = ffma2(wa[2 * i],     v.x, a0);
                a1 = ffma2(wa[2 * i + 1], v.y, a1);
                c0 = ffma2(wb[2 * i],     v.x, c0);
                c1 = ffma2(wb[2 * i + 1], v.y, c1);
            }
#pragma unroll
            for (int k = 0; k < 4; k++) {
                ulonglong2 v = xz[4 * r + k];
                y0 = ffma2(wo[2 * k],     v.x, y0);
                y1 = ffma2(wo[2 * k + 1], v.y, y1);
            }
            const size_t row = (size_t)(row0 + rr);
            g_gx[(row * 4 + g0) * 32 + f]     = sum4(a0, a1);
            g_gx[(row * 4 + g0 + 1) * 32 + f] = sum4(c0, c1);
            g_yx[(row * 2 + r) * 32 + f]      = sum4(y0, y1);
        }
        if (have)
            *(ulonglong2*)&xs[cur ^ 1][srid][sseg * 4] = nxt;
        __syncthreads();
    }
}

// ============================================================================
// K2: recurrence. CTA = 1 batch, 4 warps (warp = gate), 4 CTAs/SM (wave on
//   128 SMs). Phase 1: h-dot (gx from ring) + act + out-h chunk. Phase 2:
//   warp3 c/h; warp0 out finalize (yx rings); all: gx ring refill. 2 BAR/step.
// ============================================================================
__global__ void __launch_bounds__(128, 4)
k2_recur(const float* __restrict__ W_hh,
         const float* __restrict__ W_lin,
         float* __restrict__ out)
{
    __shared__ __align__(16) float  hb[F_DIM];
    __shared__ __align__(16) float2 gp[2][4][F_DIM];   // (act, outh_chunk)

    const int w = threadIdx.x >> 5;    // warp = gate (0:i 1:f 2:g 3:o)
    const int f = threadIdx.x & 31;
    const int b = blockIdx.x;
    const U ZERO = pack2(0.0f, 0.0f);

    U whh[16], wlh[4];
    {
        const U* ph = (const U*)(W_hh + (size_t)(w * F_DIM + f) * F_DIM);
#pragma unroll
        for (int k = 0; k < 16; k++) whh[k] = ph[k];
        const float* pl = W_lin + (size_t)f * 2 * F_DIM;
#pragma unroll
        for (int m = 0; m < 4; m++)
            wlh[m] = pack2(pl[16 * w + 4 * m], pl[16 * w + 4 * m + 2]);
    }

    const float* gxp = g_gx + ((size_t)b * T_LEN * 4 + w) * 32 + f;  // +128/t
    const float* yp0 = g_yx + ((size_t)b * T_LEN * 2 + 0) * 32 + f;  // +64/t
    const float* yp1 = g_yx + ((size_t)b * T_LEN * 2 + 1) * 32 + f;
    float*       op  = out  + (size_t)b * T_LEN * F_DIM + f;

    float c = 0.0f;              // warp3 only
    float gxr[4];                // gx ring: slot t&3 = row t
    float yr0[4], yr1[4];        // warp0: yx rings, slot k = row k (used at t=k+1)
#pragma unroll
    for (int k = 0; k < 4; k++) gxr[k] = gxp[(size_t)k * 128];
    if (w == 0) {
#pragma unroll
        for (int k = 0; k < 4; k++) { yr0[k] = yp0[(size_t)k * 64]; yr1[k] = yp1[(size_t)k * 64]; }
    }
    if (w == 3) hb[f] = 0.0f;
    __syncthreads();

    float myact = 0.0f, myohs = 0.0f;

    for (int tb = 0; tb < T_LEN; tb += 4) {
#pragma unroll
        for (int u = 0; u < 4; u++) {
            const int t   = tb + u;
            const int par = t & 1;

            // ===== phase 1 (critical): h-dot + act + out-h chunk =====
            const ulonglong2* hz = (const ulonglong2*)&hb[0];
            U a0 = pack2(gxr[t & 3], 0.f), a1 = ZERO;
#pragma unroll
            for (int i = 0; i < 8; i++) {
                ulonglong2 v = hz[i];
                a0 = ffma2(whh[2 * i],     v.x, a0);
                a1 = ffma2(whh[2 * i + 1], v.y, a1);
            }
            ulonglong2 h0 = hz[2 * w];
            ulonglong2 h1 = hz[2 * w + 1];
            U p0 = ffma2(wlh[0], h0.x, ZERO);
            U p1 = ffma2(wlh[1], h0.y, ZERO);
            p0 = ffma2(wlh[2], h1.x, p0);
            p1 = ffma2(wlh[3], h1.y, p1);

            float pre = sum4(a0, a1);
            float act = (w == 2) ? tanh_f(pre) : sig_f(pre);
            float ohs = sum4(p0, p1);
            myact = act; myohs = ohs;
            gp[par][w][f] = make_float2(act, ohs);

            // gx ring refill (off critical path)
            {
                int pt = t + 4; if (pt > T_LEN - 1) pt = T_LEN - 1;
                gxr[t & 3] = gxp[(size_t)pt * 128];
            }

            __syncthreads();   // BAR1

            // ===== phase 2 (shadow) =====
            if (w == 3) {
                float gi = gp[par][0][f].x;
                float gf = gp[par][1][f].x;
                float gg = gp[par][2][f].x;
                c = gf * c + gi * gg;
                hb[f] = myact * tanh_f(c);
            } else if (w == 0) {
                if (t > 0) {
                    float sum = myohs + gp[par][1][f].y + gp[par][2][f].y
                              + gp[par][3][f].y
                              + yr0[(t - 1) & 3] + yr1[(t - 1) & 3];
                    op[(size_t)(t - 1) * F_DIM] = tanh_acc(sum);
                }
                int pt = t + 3; if (pt > T_LEN - 1) pt = T_LEN - 1;
                yr0[(t - 1) & 3] = yp0[(size_t)pt * 64];
                yr1[(t - 1) & 3] = yp1[(size_t)pt * 64];
            }

            __syncthreads();   // BAR2: h_t visible
        }
    }

    // ---- epilogue: out_{T-1} over final h; yx[T-1] sits in slot (T-2)&3 ----
    {
        const ulonglong2* hz = (const ulonglong2*)&hb[0];
        ulonglong2 h0 = hz[2 * w];
        ulonglong2 h1 = hz[2 * w + 1];
        U p0 = ffma2(wlh[0], h0.x, ZERO);
        U p1 = ffma2(wlh[1], h0.y, ZERO);
        p0 = ffma2(wlh[2], h1.x, p0);
        p1 = ffma2(wlh[3], h1.y, p1);
        gp[0][w][f] = make_float2(0.0f, sum4(p0, p1));
        __syncthreads();
        if (w == 0) {
            float sum = gp[0][0][f].y + gp[0][1][f].y + gp[0][2][f].y
                      + gp[0][3][f].y
                      + yr0[(T_LEN - 2) & 3] + yr1[(T_LEN - 2) & 3];
            op[(size_t)(T_LEN - 1) * F_DIM] = tanh_acc(sum);
        }
    }
}

// ============================================================================
extern "C" void kernel_launch(void* const* d_in, const int* in_sizes, int n_in,
                              void* d_out, int out_size)
{
    const float* x     = (const float*)d_in[0];
    const float* W_ih  = (const float*)d_in[1];
    const float* W_hh  = (const float*)d_in[2];
    const float* b_ih  = (const float*)d_in[3];
    const float* b_hh  = (const float*)d_in[4];
    const float* W_lin = (const float*)d_in[5];
    const float* b_lin = (const float*)d_in[6];
    float* out = (float*)d_out;

    k1_xpre<<<512, 128>>>(x, W_ih, b_ih, b_hh, W_lin, b_lin);
    k2_recur<<<B_TOT, 128>>>(W_hh, W_lin, out);
}